// round 11
// baseline (speedup 1.0000x reference)
#include <cuda_runtime.h>
#include <math.h>

#define VOCAB 50257
#define BATCH 512
#define SEQ   512
#define EMBED 256
#define OUTC  5
#define EV4   (EMBED / 4)   // 64 float4 per embedding row
#define PROJ_STRIDE 8       // padded floats per vocab entry (32 B aligned)
#define GRID  394           // 394*256 = 100864 threads ~= 2*VOCAB half-row tasks

// Device scratch (mallocs forbidden). Counters zero at load and reset
// in-kernel every call -> graph-replay safe.
__device__ float        g_proj[(size_t)VOCAB * PROJ_STRIDE];  // ~1.6 MB
__device__ float        g_loss[BATCH];
__device__ unsigned int g_arrive;   // grid-barrier arrivals
__device__ unsigned int g_done;     // grid-barrier departures (guards reset)
__device__ unsigned int g_count;    // CTA completions for final mean

__global__ __launch_bounds__(256, 4)
void fused_kernel(const int*   __restrict__ input_x,
                  const int*   __restrict__ lengths,
                  const int*   __restrict__ input_y,
                  const float* __restrict__ emb,
                  const float* __restrict__ W,
                  const float* __restrict__ bias,
                  float*       __restrict__ out)
{
    __shared__ float4 s_W[OUTC * 64];   // W staged as float4 [o][c4], 5 KB
    __shared__ float  s_red[8][OUTC];
    __shared__ float  s_sum[256];
    __shared__ int    s_last;

    const int tid  = threadIdx.x;
    const int lane = tid & 31;
    const int wid  = tid >> 5;

    // Stage W into shared: 320 float4 > 256 threads -> MUST loop (round-10
    // bug: single guarded store left s_W[256..319] = garbage).
    for (int i = tid; i < OUTC * 64; i += 256)
        s_W[i] = ((const float4*)W)[i];
    __syncthreads();

    // ====== Phase 1: proj[v][o] = emb[v,:].W[o,:]  (thread-per-half-row) ====
    // Task t: row = t>>1, parity = t&1 owns float4 columns {2i+parity}.
    // Every lane executes the loop + shuffles (task CLAMPED, store
    // predicated) -- a divergent guard around __shfl_xor_sync deadlocks.
    {
        const long rawtask = (long)blockIdx.x * 256 + tid;
        const bool valid   = rawtask < 2L * VOCAB;
        const long task    = valid ? rawtask : (2L * VOCAB - 1);
        const int  row     = (int)(task >> 1);
        const int  parity  = (int)(task & 1);
        const float4* __restrict__ ev =
            (const float4*)emb + (long)row * EV4 + parity;

        float a0 = 0.f, a1 = 0.f, a2 = 0.f, a3 = 0.f, a4 = 0.f;
        #pragma unroll 4
        for (int i = 0; i < 32; i++) {
            const int c4 = 2 * i + parity;
            float4 e  = ev[2 * i];
            float4 w0 = s_W[0 * 64 + c4];
            float4 w1 = s_W[1 * 64 + c4];
            float4 w2 = s_W[2 * 64 + c4];
            float4 w3 = s_W[3 * 64 + c4];
            float4 w4 = s_W[4 * 64 + c4];
            a0 += e.x * w0.x + e.y * w0.y + e.z * w0.z + e.w * w0.w;
            a1 += e.x * w1.x + e.y * w1.y + e.z * w1.z + e.w * w1.w;
            a2 += e.x * w2.x + e.y * w2.y + e.z * w2.z + e.w * w2.w;
            a3 += e.x * w3.x + e.y * w3.y + e.z * w3.z + e.w * w3.w;
            a4 += e.x * w4.x + e.y * w4.y + e.z * w4.z + e.w * w4.w;
        }
        // Pair combine (lane ^ 1 holds the other parity of the same row).
        a0 += __shfl_xor_sync(0xffffffffu, a0, 1);
        a1 += __shfl_xor_sync(0xffffffffu, a1, 1);
        a2 += __shfl_xor_sync(0xffffffffu, a2, 1);
        a3 += __shfl_xor_sync(0xffffffffu, a3, 1);
        a4 += __shfl_xor_sync(0xffffffffu, a4, 1);
        if (valid && parity == 0) {
            *(float4*)&g_proj[(long)row * PROJ_STRIDE] =
                make_float4(a0, a1, a2, a3);
            g_proj[(long)row * PROJ_STRIDE + 4] = a4;
        }
    }

    // ====== Grid-wide barrier (all 394 CTAs co-resident) ====================
    __threadfence();            // release g_proj
    __syncthreads();
    if (tid == 0) {
        atomicAdd(&g_arrive, 1u);
        while (*(volatile unsigned int*)&g_arrive < GRID) __nanosleep(64);
        if (atomicAdd(&g_done, 1u) == GRID - 1) {   // all passed the spin
            g_arrive = 0;
            g_done   = 0;
        }
    }
    __syncthreads();
    __threadfence();            // acquire g_proj

    // ====== Phase 2: per-sample loss (CTA b, b+GRID) ========================
    for (int b = blockIdx.x; b < BATCH; b += GRID) {
        const int len = lengths[b];
        const int* xrow = input_x + b * SEQ;

        float acc[OUTC];
        #pragma unroll
        for (int o = 0; o < OUTC; o++) acc[o] = 0.f;

        if (tid < len) {
            const int t = xrow[tid];
            float4 p = *(const float4*)&g_proj[(long)t * PROJ_STRIDE];
            float  q = g_proj[(long)t * PROJ_STRIDE + 4];
            acc[0] += p.x; acc[1] += p.y; acc[2] += p.z; acc[3] += p.w; acc[4] += q;
        }
        if (tid + 256 < len) {
            const int t = xrow[tid + 256];
            float4 p = *(const float4*)&g_proj[(long)t * PROJ_STRIDE];
            float  q = g_proj[(long)t * PROJ_STRIDE + 4];
            acc[0] += p.x; acc[1] += p.y; acc[2] += p.z; acc[3] += p.w; acc[4] += q;
        }

        #pragma unroll
        for (int o = 0; o < OUTC; o++) {
            #pragma unroll
            for (int off = 16; off > 0; off >>= 1)
                acc[o] += __shfl_down_sync(0xffffffffu, acc[o], off);
        }
        if (lane == 0) {
            #pragma unroll
            for (int o = 0; o < OUTC; o++) s_red[wid][o] = acc[o];
        }
        __syncthreads();

        if (tid == 0) {
            float tot[OUTC];
            #pragma unroll
            for (int o = 0; o < OUTC; o++) {
                tot[o] = ((s_red[0][o] + s_red[1][o]) + (s_red[2][o] + s_red[3][o]))
                       + ((s_red[4][o] + s_red[5][o]) + (s_red[6][o] + s_red[7][o]));
            }
            const float inv_len = 1.0f / (float)len;
            float logits[OUTC];
            float m = -INFINITY;
            #pragma unroll
            for (int o = 0; o < OUTC; o++) {
                logits[o] = tot[o] * inv_len + bias[o];
                m = fmaxf(m, logits[o]);
            }
            float se = 0.f;
            #pragma unroll
            for (int o = 0; o < OUTC; o++) se += __expf(logits[o] - m);
            const float lse = m + __logf(se);
            const int y = input_y[b];
            g_loss[b] = lse - logits[y];
        }
        __syncthreads();   // protect s_red reuse on next loop iteration
    }

    // ====== Final mean via last-CTA pattern =================================
    if (tid == 0) {
        __threadfence();
        s_last = (atomicAdd(&g_count, 1u) == GRID - 1) ? 1 : 0;
    }
    __syncthreads();

    if (s_last) {
        __threadfence();
        s_sum[tid] = g_loss[tid] + g_loss[tid + 256];
        __syncthreads();
        #pragma unroll
        for (int off = 128; off > 0; off >>= 1) {
            if (tid < off) s_sum[tid] += s_sum[tid + off];
            __syncthreads();
        }
        if (tid == 0) {
            out[0] = s_sum[0] * (1.0f / (float)BATCH);
            g_count = 0;   // reset for next replay
        }
    }
}

extern "C" void kernel_launch(void* const* d_in, const int* in_sizes, int n_in,
                              void* d_out, int out_size)
{
    const int*   input_x = (const int*)d_in[0];
    const int*   lengths = (const int*)d_in[1];
    const int*   input_y = (const int*)d_in[2];
    const float* emb     = (const float*)d_in[3];
    const float* W       = (const float*)d_in[4];
    const float* bias    = (const float*)d_in[5];
    float* out = (float*)d_out;

    fused_kernel<<<GRID, 256>>>(input_x, lengths, input_y, emb, W, bias, out);
}

// round 12
// speedup vs baseline: 1.1618x; 1.1618x over previous
#include <cuda_runtime.h>
#include <math.h>

#define VOCAB 50257
#define BATCH 512
#define SEQ   512
#define EMBED 256
#define OUTC  5
#define EV4   (EMBED / 4)   // 64 float4 per embedding row
#define PROJ_STRIDE 8       // padded floats per vocab entry (32 B aligned)
#define GRID  432           // <= 444 co-resident slots at occupancy 3

// Device scratch (mallocs forbidden). Counters zero at load and reset
// in-kernel every call -> graph-replay safe.
__device__ float        g_proj[(size_t)VOCAB * PROJ_STRIDE];  // ~1.6 MB
__device__ float        g_loss[BATCH];
__device__ unsigned int g_arrive;   // grid-barrier arrivals
__device__ unsigned int g_done;     // grid-barrier departures (guards reset)
__device__ unsigned int g_count;    // CTA completions for final mean

__device__ __forceinline__ float dot4(const float4& a, const float4& b) {
    return a.x * b.x + a.y * b.y + a.z * b.z + a.w * b.w;
}

__global__ __launch_bounds__(256, 3)
void fused_kernel(const int*   __restrict__ input_x,
                  const int*   __restrict__ lengths,
                  const int*   __restrict__ input_y,
                  const float* __restrict__ emb,
                  const float* __restrict__ W,
                  const float* __restrict__ bias,
                  float*       __restrict__ out)
{
    __shared__ float s_red[8][OUTC];
    __shared__ float s_sum[256];
    __shared__ int   s_last;

    const int tid  = threadIdx.x;
    const int lane = tid & 31;
    const int wid  = tid >> 5;

    // ====== Phase 1: proj[v][o] = emb[v,:].W[o,:] ==========================
    // Warp-per-row (fully coalesced 1 KB row loads), W in registers,
    // software-pipelined: next row's loads are in flight during the current
    // row's FFMA + shuffle reduction.
    {
        const float4* __restrict__ embv = (const float4*)emb;
        const float4* __restrict__ Wv   = (const float4*)W;

        float4 w0[OUTC], w1[OUTC];
        #pragma unroll
        for (int o = 0; o < OUTC; o++) {
            w0[o] = Wv[o * EV4 + lane];
            w1[o] = Wv[o * EV4 + 32 + lane];
        }

        const int nwarps = GRID * 8;                 // 3456 warps
        const int gw     = (blockIdx.x << 3) + wid;  // global warp id

        float4 e0, e1;
        if (gw < VOCAB) {    // warp-uniform guard
            e0 = embv[(long)gw * EV4 + lane];
            e1 = embv[(long)gw * EV4 + 32 + lane];
        }

        for (int row = gw; row < VOCAB; row += nwarps) {   // warp-uniform
            const float4 c0 = e0, c1 = e1;
            const int nrow = row + nwarps;
            if (nrow < VOCAB) {                     // prefetch next row
                e0 = embv[(long)nrow * EV4 + lane];
                e1 = embv[(long)nrow * EV4 + 32 + lane];
            }

            float acc[OUTC];
            #pragma unroll
            for (int o = 0; o < OUTC; o++)
                acc[o] = dot4(c0, w0[o]) + dot4(c1, w1[o]);

            #pragma unroll
            for (int o = 0; o < OUTC; o++) {
                #pragma unroll
                for (int off = 16; off > 0; off >>= 1)
                    acc[o] += __shfl_down_sync(0xffffffffu, acc[o], off);
            }
            if (lane == 0) {
                *(float4*)&g_proj[(long)row * PROJ_STRIDE] =
                    make_float4(acc[0], acc[1], acc[2], acc[3]);
                g_proj[(long)row * PROJ_STRIDE + 4] = acc[4];
            }
        }
    }

    // ====== Grid-wide barrier (all 432 CTAs co-resident at occ>=3) =========
    __threadfence();            // release g_proj
    __syncthreads();
    if (tid == 0) {
        atomicAdd(&g_arrive, 1u);
        while (*(volatile unsigned int*)&g_arrive < GRID) __nanosleep(64);
        if (atomicAdd(&g_done, 1u) == GRID - 1) {   // all passed the spin
            g_arrive = 0;
            g_done   = 0;
        }
    }
    __syncthreads();
    __threadfence();            // acquire g_proj

    // ====== Phase 2: per-sample loss (CTA b, b+GRID) ========================
    for (int b = blockIdx.x; b < BATCH; b += GRID) {
        const int len = lengths[b];
        const int* xrow = input_x + b * SEQ;

        float acc[OUTC];
        #pragma unroll
        for (int o = 0; o < OUTC; o++) acc[o] = 0.f;

        if (tid < len) {
            const int t = xrow[tid];
            float4 p = *(const float4*)&g_proj[(long)t * PROJ_STRIDE];
            float  q = g_proj[(long)t * PROJ_STRIDE + 4];
            acc[0] += p.x; acc[1] += p.y; acc[2] += p.z; acc[3] += p.w; acc[4] += q;
        }
        if (tid + 256 < len) {
            const int t = xrow[tid + 256];
            float4 p = *(const float4*)&g_proj[(long)t * PROJ_STRIDE];
            float  q = g_proj[(long)t * PROJ_STRIDE + 4];
            acc[0] += p.x; acc[1] += p.y; acc[2] += p.z; acc[3] += p.w; acc[4] += q;
        }

        #pragma unroll
        for (int o = 0; o < OUTC; o++) {
            #pragma unroll
            for (int off = 16; off > 0; off >>= 1)
                acc[o] += __shfl_down_sync(0xffffffffu, acc[o], off);
        }
        if (lane == 0) {
            #pragma unroll
            for (int o = 0; o < OUTC; o++) s_red[wid][o] = acc[o];
        }
        __syncthreads();

        if (tid == 0) {
            float tot[OUTC];
            #pragma unroll
            for (int o = 0; o < OUTC; o++) {
                tot[o] = ((s_red[0][o] + s_red[1][o]) + (s_red[2][o] + s_red[3][o]))
                       + ((s_red[4][o] + s_red[5][o]) + (s_red[6][o] + s_red[7][o]));
            }
            const float inv_len = 1.0f / (float)len;
            float logits[OUTC];
            float m = -INFINITY;
            #pragma unroll
            for (int o = 0; o < OUTC; o++) {
                logits[o] = tot[o] * inv_len + bias[o];
                m = fmaxf(m, logits[o]);
            }
            float se = 0.f;
            #pragma unroll
            for (int o = 0; o < OUTC; o++) se += __expf(logits[o] - m);
            const float lse = m + __logf(se);
            const int y = input_y[b];
            g_loss[b] = lse - logits[y];
        }
        __syncthreads();   // protect s_red reuse on next loop iteration
    }

    // ====== Final mean via last-CTA pattern =================================
    if (tid == 0) {
        __threadfence();
        s_last = (atomicAdd(&g_count, 1u) == GRID - 1) ? 1 : 0;
    }
    __syncthreads();

    if (s_last) {
        __threadfence();
        s_sum[tid] = g_loss[tid] + g_loss[tid + 256];
        __syncthreads();
        #pragma unroll
        for (int off = 128; off > 0; off >>= 1) {
            if (tid < off) s_sum[tid] += s_sum[tid + off];
            __syncthreads();
        }
        if (tid == 0) {
            out[0] = s_sum[0] * (1.0f / (float)BATCH);
            g_count = 0;   // reset for next replay
        }
    }
}

extern "C" void kernel_launch(void* const* d_in, const int* in_sizes, int n_in,
                              void* d_out, int out_size)
{
    const int*   input_x = (const int*)d_in[0];
    const int*   lengths = (const int*)d_in[1];
    const int*   input_y = (const int*)d_in[2];
    const float* emb     = (const float*)d_in[3];
    const float* W       = (const float*)d_in[4];
    const float* bias    = (const float*)d_in[5];
    float* out = (float*)d_out;

    fused_kernel<<<GRID, 256>>>(input_x, lengths, input_y, emb, W, bias, out);
}